// round 15
// baseline (speedup 1.0000x reference)
#include <cuda_runtime.h>
#include <cuda_bf16.h>
#include <cstdint>
#include <cstddef>

// ---------------------------------------------------------------------------
// Problem constants (fixed instance)
// ---------------------------------------------------------------------------
#define NBOND_MAX 160001
#define NATOM_MAX 80000
#define HID       448
#define HID4      (HID/4)     // 112 float4 per row
#define KPAD_S    64          // padded K for fbonds(49)/fatoms(38)
#define KCAT      512         // fused atom GEMM K = 448 + 64

// ---------------------------------------------------------------------------
// Device scratch (allocation-free rule: __device__ globals)
// ---------------------------------------------------------------------------
__device__ float g_binput[(size_t)NBOND_MAX * HID];
__device__ float g_msgA  [(size_t)NBOND_MAX * HID];
__device__ float g_msgB  [(size_t)NBOND_MAX * HID];
__device__ float g_atomh [(size_t)NATOM_MAX * HID];

__device__ __align__(16) __nv_bfloat16 g_neih[(size_t)NBOND_MAX * HID];
__device__ __align__(16) __nv_bfloat16 g_neil[(size_t)NBOND_MAX * HID];
__device__ __align__(16) __nv_bfloat16 g_fbh [(size_t)NBOND_MAX * KPAD_S];
__device__ __align__(16) __nv_bfloat16 g_fbl [(size_t)NBOND_MAX * KPAD_S];
__device__ __align__(16) __nv_bfloat16 g_fah [(size_t)NATOM_MAX * KPAD_S];
__device__ __align__(16) __nv_bfloat16 g_fal [(size_t)NATOM_MAX * KPAD_S];
// W transposed to [n][k] (hi/lo planes)
__device__ __align__(16) __nv_bfloat16 g_Wih [(size_t)HID * KPAD_S];
__device__ __align__(16) __nv_bfloat16 g_Wil [(size_t)HID * KPAD_S];
__device__ __align__(16) __nv_bfloat16 g_Whh [(size_t)HID * HID];
__device__ __align__(16) __nv_bfloat16 g_Whl [(size_t)HID * HID];
// W_o concatenated: cols 0..447 = W_o rows 38..485 ; cols 448..511 = W_o rows 0..37 (pad)
__device__ __align__(16) __nv_bfloat16 g_Woch[(size_t)HID * KCAT];
__device__ __align__(16) __nv_bfloat16 g_Wocl[(size_t)HID * KCAT];

__device__ int   g_bgraph[(size_t)NBOND_MAX * 6];
__device__ int   g_agraph[(size_t)NATOM_MAX * 6];
__device__ int   g_mol   [(size_t)NATOM_MAX];
__device__ int   g_is64;

__device__ __forceinline__ void split_bf16(float v, __nv_bfloat16& hi, __nv_bfloat16& lo) {
    hi = __float2bfloat16(v);
    lo = __float2bfloat16(v - __bfloat162float(hi));
}

// ---------------------------------------------------------------------------
// Index dtype detection + one-shot normalization of all three index arrays.
// ---------------------------------------------------------------------------
__global__ void detect_idx64(const unsigned int* __restrict__ words, int nwords)
{
    if (threadIdx.x == 0 && blockIdx.x == 0) {
        int is64 = 1;
        for (int i = 1; i < nwords; i += 2)
            if (words[i] != 0u) { is64 = 0; break; }
        g_is64 = is64;
    }
}

__global__ void norm_all(const void* __restrict__ bg, const void* __restrict__ ag,
                         const void* __restrict__ mi,
                         int* __restrict__ dbg, int* __restrict__ dag, int* __restrict__ dmi,
                         int nb6, int na6, int na)
{
    int i = blockIdx.x * blockDim.x + threadIdx.x;
    const int is64 = g_is64;
    if (i < nb6) {
        dbg[i] = is64 ? (int)((const long long*)bg)[i] : ((const int*)bg)[i];
    } else if (i < nb6 + na6) {
        int j = i - nb6;
        dag[j] = is64 ? (int)((const long long*)ag)[j] : ((const int*)ag)[j];
    } else if (i < nb6 + na6 + na) {
        int j = i - nb6 - na6;
        dmi[j] = is64 ? (int)((const long long*)mi)[j] : ((const int*)mi)[j];
    }
}

// ---------------------------------------------------------------------------
// One-shot operand prep: split fbonds/fatoms (row-major, K-padded) and
// transpose+split W_i / W_h / W_o(concat) into bf16 hi/lo planes.
// ---------------------------------------------------------------------------
__global__ void prep_all(const float* __restrict__ fbonds, const float* __restrict__ fatoms,
                         const float* __restrict__ W_i, const float* __restrict__ W_h,
                         const float* __restrict__ W_o,
                         __nv_bfloat16* __restrict__ fbh, __nv_bfloat16* __restrict__ fbl,
                         __nv_bfloat16* __restrict__ fah, __nv_bfloat16* __restrict__ fal,
                         __nv_bfloat16* __restrict__ Wih, __nv_bfloat16* __restrict__ Wil,
                         __nv_bfloat16* __restrict__ Whh, __nv_bfloat16* __restrict__ Whl,
                         __nv_bfloat16* __restrict__ Woch, __nv_bfloat16* __restrict__ Wocl,
                         int n_bonds, int n_atoms, int K_in, int K_atom)
{
    const size_t s0 = (size_t)n_bonds * KPAD_S;
    const size_t s1 = (size_t)n_atoms * KPAD_S;
    const size_t s2 = (size_t)HID * KPAD_S;
    const size_t s3 = (size_t)HID * HID;
    const size_t s4 = (size_t)HID * KCAT;
    size_t idx = (size_t)blockIdx.x * blockDim.x + threadIdx.x;
    float v;
    __nv_bfloat16 h, l;
    if (idx < s0) {
        int r = (int)(idx / KPAD_S), c = (int)(idx % KPAD_S);
        v = (c < K_in) ? __ldg(&fbonds[(size_t)r * K_in + c]) : 0.f;
        split_bf16(v, h, l); fbh[idx] = h; fbl[idx] = l; return;
    }
    idx -= s0;
    if (idx < s1) {
        int r = (int)(idx / KPAD_S), c = (int)(idx % KPAD_S);
        v = (c < K_atom) ? __ldg(&fatoms[(size_t)r * K_atom + c]) : 0.f;
        split_bf16(v, h, l); fah[idx] = h; fal[idx] = l; return;
    }
    idx -= s1;
    if (idx < s2) {
        int n = (int)(idx / KPAD_S), k = (int)(idx % KPAD_S);
        v = (k < K_in) ? __ldg(&W_i[(size_t)k * HID + n]) : 0.f;
        split_bf16(v, h, l); Wih[idx] = h; Wil[idx] = l; return;
    }
    idx -= s2;
    if (idx < s3) {
        int n = (int)(idx / HID), k = (int)(idx % HID);
        v = __ldg(&W_h[(size_t)k * HID + n]);
        split_bf16(v, h, l); Whh[idx] = h; Whl[idx] = l; return;
    }
    idx -= s3;
    if (idx < s4) {
        int n = (int)(idx / KCAT), k = (int)(idx % KCAT);
        if (k < HID) v = __ldg(&W_o[(size_t)(K_atom + k) * HID + n]);
        else {
            int kk = k - HID;
            v = (kk < K_atom) ? __ldg(&W_o[(size_t)kk * HID + n]) : 0.f;
        }
        split_bf16(v, h, l); Woch[idx] = h; Wocl[idx] = l;
    }
}

// ---------------------------------------------------------------------------
// 3xBF16 GEMM, pre-split operands, ldmatrix fragments, cp.async 3-stage pipe
// (one __syncthreads per K-tile), 3 CTAs/SM (73.7 KB smem, unpadded strides).
// C[M x 448] = A[M x K] @ W (W pre-transposed [n][k]).
// CONCAT: A = [A | A2] along K, switch at K1 (per-K-tile granularity).
// Block tile 128x64x32, 256 threads, warp tile 32x32 (2x4 m16n8k16 tiles).
// ---------------------------------------------------------------------------
#define BM 128
#define BN 64
#define BK 32
#define ASTR 32                 // bf16 row stride for A  [m][k] (64 B, unpadded)
#define BSTR 32                 // bf16 row stride for B^T [n][k]
#define A_SZ (BM * ASTR)        // 4096 bf16
#define B_SZ (BN * BSTR)        // 2048 bf16
#define BUF_SZ (2 * A_SZ + 2 * B_SZ)   // 12288 bf16 = 24576 B per stage
#define BUF_B  (BUF_SZ * 2)
#define N_STAGE 3
#define GEMM_SMEM (N_STAGE * BUF_B)    // 73728 bytes -> 3 CTAs/SM

__device__ __forceinline__ uint32_t smem_u32(const void* p) {
    uint32_t a;
    asm("{ .reg .u64 t; cvta.to.shared.u64 t, %1; cvt.u32.u64 %0, t; }" : "=r"(a) : "l"(p));
    return a;
}

__device__ __forceinline__ void mma_bf16(float* d, const uint32_t* a, const uint32_t* b) {
    asm volatile(
        "mma.sync.aligned.m16n8k16.row.col.f32.bf16.bf16.f32 "
        "{%0,%1,%2,%3}, {%4,%5,%6,%7}, {%8,%9}, {%0,%1,%2,%3};\n"
        : "+f"(d[0]), "+f"(d[1]), "+f"(d[2]), "+f"(d[3])
        : "r"(a[0]), "r"(a[1]), "r"(a[2]), "r"(a[3]), "r"(b[0]), "r"(b[1]));
}

__device__ __forceinline__ void ldsm_x4(uint32_t& r0, uint32_t& r1, uint32_t& r2, uint32_t& r3,
                                        uint32_t addr) {
    asm volatile("ldmatrix.sync.aligned.m8n8.x4.shared.b16 {%0,%1,%2,%3}, [%4];"
        : "=r"(r0), "=r"(r1), "=r"(r2), "=r"(r3) : "r"(addr));
}

__device__ __forceinline__ void cp16(uint32_t dst, const void* src, int src_sz) {
    asm volatile("cp.async.cg.shared.global [%0], [%1], 16, %2;"
        :: "r"(dst), "l"(src), "r"(src_sz) : "memory");
}
#define CP_COMMIT() asm volatile("cp.async.commit_group;" ::: "memory")

template<bool CONCAT, bool RELU, bool HAS_ADD, bool HAS_BIAS>
__global__ void __launch_bounds__(256, 3)
gemm_pre(const __nv_bfloat16* __restrict__ Ahi,
         const __nv_bfloat16* __restrict__ Alo, int lda,    // bf16 elems, mult of 8
         const __nv_bfloat16* __restrict__ A2hi,            // concat source (k >= K1)
         const __nv_bfloat16* __restrict__ A2lo, int lda2, int K1,
         const __nv_bfloat16* __restrict__ Wthi,            // [448 n x ldb k]
         const __nv_bfloat16* __restrict__ Wtlo, int ldb,
         const float* __restrict__ addrow,                  // [M x 448] or null
         const float* __restrict__ bias,                    // [448] or null
         float* __restrict__ out,
         int M, int K)                                      // K = padded, mult of 32
{
    extern __shared__ __nv_bfloat16 smem[];
    const uint32_t smb = smem_u32(smem);

    const int tid  = threadIdx.x;
    const int m0   = blockIdx.y * BM;
    const int n0   = blockIdx.x * BN;
    const int warp = tid >> 5, lane = tid & 31;
    const int wm   = (warp & 3) * 32;      // 4 warps along M
    const int wn   = (warp >> 2) * 32;     // 2 warps along N
    const int g    = lane >> 2, tig = lane & 3;

    float acc[2][4][4] = {};

    // ldmatrix per-thread byte offsets (within a hi/lo plane)
    uint32_t aoff[2];
    #pragma unroll
    for (int tm = 0; tm < 2; ++tm)
        aoff[tm] = (uint32_t)(((wm + tm * 16 + (lane & 15)) * ASTR + 8 * (lane >> 4)) * 2);
    uint32_t boff[2];
    #pragma unroll
    for (int pr = 0; pr < 2; ++pr)
        boff[pr] = (uint32_t)(((wn + pr * 16 + 8 * (lane >> 4) + (lane & 7)) * BSTR
                               + 8 * ((lane >> 3) & 1)) * 2);

    // cp.async tile coordinates
    const int lar = tid >> 2, lac = tid & 3;     // A: row (+64 for i=1), 16B chunk
    const int lbn = tid >> 2, lbc = tid & 3;     // B: n-row, 16B chunk

    const int nk = K / BK;

    auto issue_tile = [&](int kt, int s) {
        const int k0 = kt * BK;
        const uint32_t b0 = smb + (uint32_t)(s * BUF_B);
        const uint32_t bA = b0 + (uint32_t)((lar * ASTR + 8 * lac) * 2);
        const __nv_bfloat16* sAh = Ahi;
        const __nv_bfloat16* sAl = Alo;
        int ld = lda, kc = k0;
        if (CONCAT && k0 >= K1) { sAh = A2hi; sAl = A2lo; ld = lda2; kc = k0 - K1; }
        #pragma unroll
        for (int i = 0; i < 2; ++i) {
            int r = lar + i * 64;
            int ok = (m0 + r < M);
            int rr = ok ? (m0 + r) : 0;
            size_t off = (size_t)rr * ld + kc + 8 * lac;
            int sz = ok ? 16 : 0;
            cp16(bA + (uint32_t)(i * 64 * ASTR * 2),              &sAh[off], sz);
            cp16(bA + (uint32_t)(i * 64 * ASTR * 2) + A_SZ * 2,   &sAl[off], sz);
        }
        {
            size_t off = (size_t)(n0 + lbn) * ldb + k0 + 8 * lbc;
            uint32_t bB = b0 + 2 * A_SZ * 2 + (uint32_t)((lbn * BSTR + 8 * lbc) * 2);
            cp16(bB,            &Wthi[off], 16);
            cp16(bB + B_SZ * 2, &Wtlo[off], 16);
        }
    };

    // prologue: two tiles in flight
    issue_tile(0, 0); CP_COMMIT();
    if (nk > 1) { issue_tile(1, 1); CP_COMMIT(); }

    for (int kt = 0; kt < nk; ++kt) {
        const int s = kt % N_STAGE;
        if (kt < nk - 1) asm volatile("cp.async.wait_group 1;" ::: "memory");
        else             asm volatile("cp.async.wait_group 0;" ::: "memory");
        __syncthreads();
        // stage (kt+2)%3 == (kt-1)%3 was consumed in iter kt-1; all threads are
        // past that iteration's reads (they reached this barrier), so it's free.
        if (kt + 2 < nk) { issue_tile(kt + 2, (kt + 2) % N_STAGE); CP_COMMIT(); }

        const uint32_t bAhi = smb + (uint32_t)(s * BUF_B);
        const uint32_t bAlo = bAhi + A_SZ * 2;
        const uint32_t bBhi = bAlo + A_SZ * 2;
        const uint32_t bBlo = bBhi + B_SZ * 2;

        #pragma unroll
        for (int half = 0; half < 2; ++half) {
            const uint32_t kb = half * 16 * 2;   // k byte offset
            uint32_t ah[2][4], al[2][4], bh[4][2], bl[4][2];
            #pragma unroll
            for (int tm = 0; tm < 2; ++tm) {
                ldsm_x4(ah[tm][0], ah[tm][1], ah[tm][2], ah[tm][3], bAhi + aoff[tm] + kb);
                ldsm_x4(al[tm][0], al[tm][1], al[tm][2], al[tm][3], bAlo + aoff[tm] + kb);
            }
            #pragma unroll
            for (int pr = 0; pr < 2; ++pr) {
                ldsm_x4(bh[2*pr][0], bh[2*pr][1], bh[2*pr+1][0], bh[2*pr+1][1],
                        bBhi + boff[pr] + kb);
                ldsm_x4(bl[2*pr][0], bl[2*pr][1], bl[2*pr+1][0], bl[2*pr+1][1],
                        bBlo + boff[pr] + kb);
            }
            #pragma unroll
            for (int tm = 0; tm < 2; ++tm)
                #pragma unroll
                for (int tn = 0; tn < 4; ++tn) {
                    mma_bf16(acc[tm][tn], ah[tm], bh[tn]);
                    mma_bf16(acc[tm][tn], ah[tm], bl[tn]);
                    mma_bf16(acc[tm][tn], al[tm], bh[tn]);
                }
        }
    }

    // --- epilogue: (c0,c1)/(c2,c3) are col pairs at rows r / r+8 ---
    #pragma unroll
    for (int tm = 0; tm < 2; ++tm) {
        #pragma unroll
        for (int half = 0; half < 2; ++half) {
            int row = m0 + wm + tm * 16 + g + half * 8;
            if (row >= M) continue;
            #pragma unroll
            for (int tn = 0; tn < 4; ++tn) {
                int col = n0 + wn + tn * 8 + 2 * tig;
                float v0 = acc[tm][tn][half * 2 + 0];
                float v1 = acc[tm][tn][half * 2 + 1];
                if (HAS_ADD) {
                    float2 a2 = *(const float2*)&addrow[(size_t)row * HID + col];
                    v0 += a2.x; v1 += a2.y;
                }
                if (HAS_BIAS) { v0 += __ldg(&bias[col]); v1 += __ldg(&bias[col + 1]); }
                if (RELU) { v0 = fmaxf(v0, 0.f); v1 = fmaxf(v1, 0.f); }
                *(float2*)&out[(size_t)row * HID + col] = make_float2(v0, v1);
            }
        }
    }
}

// ---------------------------------------------------------------------------
// gather-sum over 6 padded neighbors with ON-LOAD RELU, writes bf16 hi/lo
// planes. Sources hold PRE-relu messages; relu is applied here.
// block (112, 4); per-row indices deduped via smem.
// ---------------------------------------------------------------------------
__global__ void gather6_split(const float4* __restrict__ src,
                              const int* __restrict__ idx,
                              __nv_bfloat16* __restrict__ hi,
                              __nv_bfloat16* __restrict__ lo, int n)
{
    __shared__ int sIdx[24];
    int flat = threadIdx.y * 112 + threadIdx.x;
    if (flat < 24) {
        int r = flat / 6, j = flat % 6;
        int row = blockIdx.x * 4 + r;
        sIdx[flat] = (row < n) ? __ldg(&idx[(size_t)row * 6 + j]) : 0;
    }
    __syncthreads();

    int row = blockIdx.x * 4 + threadIdx.y;
    if (row >= n) return;
    int c = threadIdx.x;  // 0..111
    float4 acc = make_float4(0.f, 0.f, 0.f, 0.f);
    #pragma unroll
    for (int j = 0; j < 6; ++j) {
        int b = sIdx[threadIdx.y * 6 + j];
        float4 v = __ldg(&src[(size_t)b * HID4 + c]);
        acc.x += fmaxf(v.x, 0.f); acc.y += fmaxf(v.y, 0.f);
        acc.z += fmaxf(v.z, 0.f); acc.w += fmaxf(v.w, 0.f);
    }
    __nv_bfloat16 h0, l0, h1, l1, h2, l2, h3, l3;
    split_bf16(acc.x, h0, l0); split_bf16(acc.y, h1, l1);
    split_bf16(acc.z, h2, l2); split_bf16(acc.w, h3, l3);
    __nv_bfloat162 ph01 = __halves2bfloat162(h0, h1);
    __nv_bfloat162 ph23 = __halves2bfloat162(h2, h3);
    __nv_bfloat162 pl01 = __halves2bfloat162(l0, l1);
    __nv_bfloat162 pl23 = __halves2bfloat162(l2, l3);
    uint2 uh = make_uint2(*(uint32_t*)&ph01, *(uint32_t*)&ph23);
    uint2 ul = make_uint2(*(uint32_t*)&pl01, *(uint32_t*)&pl23);
    *(uint2*)&hi[(size_t)row * HID + 4 * c] = uh;
    *(uint2*)&lo[(size_t)row * HID + 4 * c] = ul;
}

// ---------------------------------------------------------------------------
// segment mean over sorted mol_idx
// ---------------------------------------------------------------------------
__global__ void segment_mean(const float4* __restrict__ atomh,
                             const int* __restrict__ mol,
                             float4* __restrict__ out, int n_atoms)
{
    int m = blockIdx.x;
    int c = threadIdx.x;  // 0..111
    int lo = 0, hi = n_atoms;
    while (lo < hi) { int mid = (lo + hi) >> 1; if (__ldg(&mol[mid]) < m) lo = mid + 1; else hi = mid; }
    int lo2 = lo, hi2 = n_atoms;
    while (lo2 < hi2) { int mid = (lo2 + hi2) >> 1; if (__ldg(&mol[mid]) < m + 1) lo2 = mid + 1; else hi2 = mid; }
    float4 acc = make_float4(0.f, 0.f, 0.f, 0.f);
    for (int a = lo; a < lo2; ++a) {
        float4 v = __ldg(&atomh[(size_t)a * HID4 + c]);
        acc.x += v.x; acc.y += v.y; acc.z += v.z; acc.w += v.w;
    }
    float inv = 1.f / fmaxf((float)(lo2 - lo), 1.f);
    out[(size_t)m * HID4 + c] = make_float4(acc.x * inv, acc.y * inv, acc.z * inv, acc.w * inv);
}

// ---------------------------------------------------------------------------
// host launcher
// ---------------------------------------------------------------------------
static void set_smem(const void* f, int bytes) {
    cudaFuncSetAttribute(f, cudaFuncAttributeMaxDynamicSharedMemorySize, bytes);
}
#define SYMADDR(p, s) cudaGetSymbolAddress((void**)&(p), s)

extern "C" void kernel_launch(void* const* d_in, const int* in_sizes, int n_in,
                              void* d_out, int out_size)
{
    const float* fatoms  = (const float*)d_in[0];
    const float* fbonds  = (const float*)d_in[1];
    const float* W_i     = (const float*)d_in[2];
    const float* W_h     = (const float*)d_in[3];
    const float* W_o     = (const float*)d_in[4];
    const float* b_o     = (const float*)d_in[5];
    const void*  agraph  = d_in[6];
    const void*  bgraph  = d_in[7];
    const void*  mol_idx = d_in[8];

    const int n_atoms = in_sizes[8];            // 80000
    const int n_bonds = in_sizes[7] / 6;        // 160001
    const int n_mols  = out_size / HID;         // 4000
    const int K_in    = in_sizes[2] / HID;      // 49
    const int K_atom  = in_sizes[0] / n_atoms;  // 38

    float *binput, *msgA, *msgB, *atomh;
    __nv_bfloat16 *neih, *neil, *fbh, *fbl, *fah, *fal;
    __nv_bfloat16 *Wih, *Wil, *Whh, *Whl, *Woch, *Wocl;
    int *bgr, *agr, *mol;
    SYMADDR(binput, g_binput); SYMADDR(msgA, g_msgA); SYMADDR(msgB, g_msgB);
    SYMADDR(atomh, g_atomh);
    SYMADDR(neih, g_neih); SYMADDR(neil, g_neil);
    SYMADDR(fbh, g_fbh);   SYMADDR(fbl, g_fbl);
    SYMADDR(fah, g_fah);   SYMADDR(fal, g_fal);
    SYMADDR(Wih, g_Wih);   SYMADDR(Wil, g_Wil);
    SYMADDR(Whh, g_Whh);   SYMADDR(Whl, g_Whl);
    SYMADDR(Woch, g_Woch); SYMADDR(Wocl, g_Wocl);
    SYMADDR(bgr, g_bgraph); SYMADDR(agr, g_agraph); SYMADDR(mol, g_mol);

    set_smem((const void*)gemm_pre<false, false, false, false>, GEMM_SMEM);
    set_smem((const void*)gemm_pre<false, false, true,  false>, GEMM_SMEM);
    set_smem((const void*)gemm_pre<true,  true,  false, true >, GEMM_SMEM);

    // 0) index normalization + one-shot operand prep
    detect_idx64<<<1, 32>>>((const unsigned int*)bgraph, 512);
    {
        int total = n_bonds * 6 + n_atoms * 6 + n_atoms;
        norm_all<<<(total + 255) / 256, 256>>>(bgraph, agraph, mol_idx,
                                               bgr, agr, mol,
                                               n_bonds * 6, n_atoms * 6, n_atoms);
    }
    {
        size_t total = (size_t)n_bonds * KPAD_S + (size_t)n_atoms * KPAD_S
                     + (size_t)HID * KPAD_S + (size_t)HID * HID + (size_t)HID * KCAT;
        prep_all<<<(unsigned)((total + 255) / 256), 256>>>(
            fbonds, fatoms, W_i, W_h, W_o,
            fbh, fbl, fah, fal, Wih, Wil, Whh, Whl, Woch, Wocl,
            n_bonds, n_atoms, K_in, K_atom);
    }

    dim3 blk(256);
    dim3 grdB(HID / BN, (n_bonds + BM - 1) / BM);   // (7, 1251)
    dim3 grdA(HID / BN, (n_atoms + BM - 1) / BM);   // (7, 625)
    dim3 gblk(HID4, 4);

    // 1) binput = fbonds @ W_i  (raw only; relu applied by consumers)
    gemm_pre<false, false, false, false><<<grdB, blk, GEMM_SMEM>>>(
        fbh, fbl, KPAD_S, nullptr, nullptr, 0, 1 << 30,
        Wih, Wil, KPAD_S, nullptr, nullptr,
        binput, n_bonds, KPAD_S);

    // 2) message-passing iterations (DEPTH-1 = 4); messages stored PRE-relu,
    //    gather applies relu on load.
    float* cur = binput;      // message_0 = relu(binput) — relu in gather
    float* nxt = msgA;
    float* spare = msgB;
    for (int it = 0; it < 4; ++it) {
        gather6_split<<<(n_bonds + 3) / 4, gblk>>>((const float4*)cur, bgr,
                                                   neih, neil, n_bonds);
        gemm_pre<false, false, true, false><<<grdB, blk, GEMM_SMEM>>>(
            neih, neil, HID, nullptr, nullptr, 0, 1 << 30,
            Whh, Whl, HID, binput, nullptr,
            nxt, n_bonds, HID);
        float* old = cur;
        cur = nxt;
        nxt = (it == 0) ? spare : old;    // never overwrite binput
    }

    // 3) atom readout: gather (relu on load), then fused
    //    atomh = relu([nei | fatoms] @ Woc + b_o)
    gather6_split<<<(n_atoms + 3) / 4, gblk>>>((const float4*)cur, agr,
                                               neih, neil, n_atoms);
    gemm_pre<true, true, false, true><<<grdA, blk, GEMM_SMEM>>>(
        neih, neil, HID, fah, fal, KPAD_S, HID,
        Woch, Wocl, KCAT, nullptr, b_o,
        atomh, n_atoms, KCAT);

    // 4) per-molecule mean (sorted mol_idx, no atomics)
    segment_mean<<<n_mols, HID4>>>((const float4*)atomh, mol,
                                   (float4*)d_out, n_atoms);
}

// round 16
// speedup vs baseline: 1.7374x; 1.7374x over previous
#include <cuda_runtime.h>
#include <cuda_bf16.h>
#include <cstdint>
#include <cstddef>

// ---------------------------------------------------------------------------
// Problem constants (fixed instance)
// ---------------------------------------------------------------------------
#define NBOND_MAX 160001
#define NATOM_MAX 80000
#define HID       448
#define HID4      (HID/4)     // 112 float4 per row
#define KPAD_S    64          // padded K for fbonds(49)/fatoms(38)
#define KCAT      512         // fused atom GEMM K = 448 + 64

// ---------------------------------------------------------------------------
// Device scratch (allocation-free rule: __device__ globals)
// ---------------------------------------------------------------------------
__device__ float g_binput[(size_t)NBOND_MAX * HID];
__device__ float g_msgA  [(size_t)NBOND_MAX * HID];
__device__ float g_msgB  [(size_t)NBOND_MAX * HID];
__device__ float g_atomh [(size_t)NATOM_MAX * HID];

__device__ __align__(16) __nv_bfloat16 g_neih[(size_t)NBOND_MAX * HID];
__device__ __align__(16) __nv_bfloat16 g_neil[(size_t)NBOND_MAX * HID];
__device__ __align__(16) __nv_bfloat16 g_fbh [(size_t)NBOND_MAX * KPAD_S];
__device__ __align__(16) __nv_bfloat16 g_fbl [(size_t)NBOND_MAX * KPAD_S];
__device__ __align__(16) __nv_bfloat16 g_fah [(size_t)NATOM_MAX * KPAD_S];
__device__ __align__(16) __nv_bfloat16 g_fal [(size_t)NATOM_MAX * KPAD_S];
// W transposed to [n][k] (hi/lo planes)
__device__ __align__(16) __nv_bfloat16 g_Wih [(size_t)HID * KPAD_S];
__device__ __align__(16) __nv_bfloat16 g_Wil [(size_t)HID * KPAD_S];
__device__ __align__(16) __nv_bfloat16 g_Whh [(size_t)HID * HID];
__device__ __align__(16) __nv_bfloat16 g_Whl [(size_t)HID * HID];
// W_o concatenated: cols 0..447 = W_o rows 38..485 ; cols 448..511 = W_o rows 0..37 (pad)
__device__ __align__(16) __nv_bfloat16 g_Woch[(size_t)HID * KCAT];
__device__ __align__(16) __nv_bfloat16 g_Wocl[(size_t)HID * KCAT];

__device__ int   g_bgraph[(size_t)NBOND_MAX * 6];
__device__ int   g_agraph[(size_t)NATOM_MAX * 6];
__device__ int   g_mol   [(size_t)NATOM_MAX];
__device__ int   g_is64;

__device__ __forceinline__ void split_bf16(float v, __nv_bfloat16& hi, __nv_bfloat16& lo) {
    hi = __float2bfloat16(v);
    lo = __float2bfloat16(v - __bfloat162float(hi));
}

// ---------------------------------------------------------------------------
// Index dtype detection + one-shot normalization of all three index arrays.
// ---------------------------------------------------------------------------
__global__ void detect_idx64(const unsigned int* __restrict__ words, int nwords)
{
    if (threadIdx.x == 0 && blockIdx.x == 0) {
        int is64 = 1;
        for (int i = 1; i < nwords; i += 2)
            if (words[i] != 0u) { is64 = 0; break; }
        g_is64 = is64;
    }
}

__global__ void norm_all(const void* __restrict__ bg, const void* __restrict__ ag,
                         const void* __restrict__ mi,
                         int* __restrict__ dbg, int* __restrict__ dag, int* __restrict__ dmi,
                         int nb6, int na6, int na)
{
    int i = blockIdx.x * blockDim.x + threadIdx.x;
    const int is64 = g_is64;
    if (i < nb6) {
        dbg[i] = is64 ? (int)((const long long*)bg)[i] : ((const int*)bg)[i];
    } else if (i < nb6 + na6) {
        int j = i - nb6;
        dag[j] = is64 ? (int)((const long long*)ag)[j] : ((const int*)ag)[j];
    } else if (i < nb6 + na6 + na) {
        int j = i - nb6 - na6;
        dmi[j] = is64 ? (int)((const long long*)mi)[j] : ((const int*)mi)[j];
    }
}

// ---------------------------------------------------------------------------
// One-shot operand prep: split fbonds/fatoms (row-major, K-padded) and
// transpose+split W_i / W_h / W_o(concat) into bf16 hi/lo planes.
// ---------------------------------------------------------------------------
__global__ void prep_all(const float* __restrict__ fbonds, const float* __restrict__ fatoms,
                         const float* __restrict__ W_i, const float* __restrict__ W_h,
                         const float* __restrict__ W_o,
                         __nv_bfloat16* __restrict__ fbh, __nv_bfloat16* __restrict__ fbl,
                         __nv_bfloat16* __restrict__ fah, __nv_bfloat16* __restrict__ fal,
                         __nv_bfloat16* __restrict__ Wih, __nv_bfloat16* __restrict__ Wil,
                         __nv_bfloat16* __restrict__ Whh, __nv_bfloat16* __restrict__ Whl,
                         __nv_bfloat16* __restrict__ Woch, __nv_bfloat16* __restrict__ Wocl,
                         int n_bonds, int n_atoms, int K_in, int K_atom)
{
    const size_t s0 = (size_t)n_bonds * KPAD_S;
    const size_t s1 = (size_t)n_atoms * KPAD_S;
    const size_t s2 = (size_t)HID * KPAD_S;
    const size_t s3 = (size_t)HID * HID;
    const size_t s4 = (size_t)HID * KCAT;
    size_t idx = (size_t)blockIdx.x * blockDim.x + threadIdx.x;
    float v;
    __nv_bfloat16 h, l;
    if (idx < s0) {
        int r = (int)(idx / KPAD_S), c = (int)(idx % KPAD_S);
        v = (c < K_in) ? __ldg(&fbonds[(size_t)r * K_in + c]) : 0.f;
        split_bf16(v, h, l); fbh[idx] = h; fbl[idx] = l; return;
    }
    idx -= s0;
    if (idx < s1) {
        int r = (int)(idx / KPAD_S), c = (int)(idx % KPAD_S);
        v = (c < K_atom) ? __ldg(&fatoms[(size_t)r * K_atom + c]) : 0.f;
        split_bf16(v, h, l); fah[idx] = h; fal[idx] = l; return;
    }
    idx -= s1;
    if (idx < s2) {
        int n = (int)(idx / KPAD_S), k = (int)(idx % KPAD_S);
        v = (k < K_in) ? __ldg(&W_i[(size_t)k * HID + n]) : 0.f;
        split_bf16(v, h, l); Wih[idx] = h; Wil[idx] = l; return;
    }
    idx -= s2;
    if (idx < s3) {
        int n = (int)(idx / HID), k = (int)(idx % HID);
        v = __ldg(&W_h[(size_t)k * HID + n]);
        split_bf16(v, h, l); Whh[idx] = h; Whl[idx] = l; return;
    }
    idx -= s3;
    if (idx < s4) {
        int n = (int)(idx / KCAT), k = (int)(idx % KCAT);
        if (k < HID) v = __ldg(&W_o[(size_t)(K_atom + k) * HID + n]);
        else {
            int kk = k - HID;
            v = (kk < K_atom) ? __ldg(&W_o[(size_t)kk * HID + n]) : 0.f;
        }
        split_bf16(v, h, l); Woch[idx] = h; Wocl[idx] = l;
    }
}

// ---------------------------------------------------------------------------
// 3xBF16 GEMM, pre-split operands, ldmatrix fragments, cp.async 3-stage pipe
// (one __syncthreads per K-tile), 3 CTAs/SM. Unpadded 64B smem rows with a
// chunk XOR swizzle: stored 16B-chunk index = c ^ ((row>>1)&3). Conflict-free:
// in each 8-row LDSM phase the 4 even rows take keys {0,1,2,3} (distinct
// chunks -> bytes 0..63 of the 128B span), odd rows likewise bytes 64..127.
// C[M x 448] = A[M x K] @ W (W pre-transposed [n][k]).
// CONCAT: A = [A | A2] along K, switch at K1 (per-K-tile granularity).
// Block tile 128x64x32, 256 threads, warp tile 32x32 (2x4 m16n8k16 tiles).
// ---------------------------------------------------------------------------
#define BM 128
#define BN 64
#define BK 32
#define ASTR 32                 // bf16 row stride for A  [m][k] (64 B, swizzled)
#define BSTR 32                 // bf16 row stride for B^T [n][k]
#define A_SZ (BM * ASTR)        // 4096 bf16 = 8192 B
#define B_SZ (BN * BSTR)        // 2048 bf16 = 4096 B
#define BUF_SZ (2 * A_SZ + 2 * B_SZ)   // 12288 bf16 = 24576 B per stage
#define BUF_B  (BUF_SZ * 2)
#define N_STAGE 3
#define GEMM_SMEM (N_STAGE * BUF_B)    // 73728 bytes -> 3 CTAs/SM

__device__ __forceinline__ uint32_t smem_u32(const void* p) {
    uint32_t a;
    asm("{ .reg .u64 t; cvta.to.shared.u64 t, %1; cvt.u32.u64 %0, t; }" : "=r"(a) : "l"(p));
    return a;
}

__device__ __forceinline__ void mma_bf16(float* d, const uint32_t* a, const uint32_t* b) {
    asm volatile(
        "mma.sync.aligned.m16n8k16.row.col.f32.bf16.bf16.f32 "
        "{%0,%1,%2,%3}, {%4,%5,%6,%7}, {%8,%9}, {%0,%1,%2,%3};\n"
        : "+f"(d[0]), "+f"(d[1]), "+f"(d[2]), "+f"(d[3])
        : "r"(a[0]), "r"(a[1]), "r"(a[2]), "r"(a[3]), "r"(b[0]), "r"(b[1]));
}

__device__ __forceinline__ void ldsm_x4(uint32_t& r0, uint32_t& r1, uint32_t& r2, uint32_t& r3,
                                        uint32_t addr) {
    asm volatile("ldmatrix.sync.aligned.m8n8.x4.shared.b16 {%0,%1,%2,%3}, [%4];"
        : "=r"(r0), "=r"(r1), "=r"(r2), "=r"(r3) : "r"(addr));
}

__device__ __forceinline__ void cp16(uint32_t dst, const void* src, int src_sz) {
    asm volatile("cp.async.cg.shared.global [%0], [%1], 16, %2;"
        :: "r"(dst), "l"(src), "r"(src_sz) : "memory");
}
#define CP_COMMIT() asm volatile("cp.async.commit_group;" ::: "memory")

template<bool CONCAT, bool RELU, bool HAS_ADD, bool HAS_BIAS>
__global__ void __launch_bounds__(256, 3)
gemm_pre(const __nv_bfloat16* __restrict__ Ahi,
         const __nv_bfloat16* __restrict__ Alo, int lda,    // bf16 elems, mult of 8
         const __nv_bfloat16* __restrict__ A2hi,            // concat source (k >= K1)
         const __nv_bfloat16* __restrict__ A2lo, int lda2, int K1,
         const __nv_bfloat16* __restrict__ Wthi,            // [448 n x ldb k]
         const __nv_bfloat16* __restrict__ Wtlo, int ldb,
         const float* __restrict__ addrow,                  // [M x 448] or null
         const float* __restrict__ bias,                    // [448] or null
         float* __restrict__ out,
         int M, int K)                                      // K = padded, mult of 32
{
    extern __shared__ __nv_bfloat16 smem[];
    const uint32_t smb = smem_u32(smem);

    const int tid  = threadIdx.x;
    const int m0   = blockIdx.y * BM;
    const int n0   = blockIdx.x * BN;
    const int warp = tid >> 5, lane = tid & 31;
    const int wm   = (warp & 3) * 32;      // 4 warps along M
    const int wn   = (warp >> 2) * 32;     // 2 warps along N
    const int g    = lane >> 2, tig = lane & 3;

    float acc[2][4][4] = {};

    // ldmatrix per-thread row byte-offset + swizzle key (within a hi/lo plane)
    uint32_t arow[2]; uint32_t akey[2];
    #pragma unroll
    for (int tm = 0; tm < 2; ++tm) {
        int r = wm + tm * 16 + (lane & 15);
        arow[tm] = (uint32_t)(r * 64);
        akey[tm] = (uint32_t)((r >> 1) & 3);
    }
    const uint32_t acb = (uint32_t)(lane >> 4);          // A col chunk bit (0/1)
    uint32_t brow[2]; uint32_t bkey[2];
    #pragma unroll
    for (int pr = 0; pr < 2; ++pr) {
        int r = wn + pr * 16 + 8 * (lane >> 4) + (lane & 7);
        brow[pr] = (uint32_t)(r * 64);
        bkey[pr] = (uint32_t)((r >> 1) & 3);
    }
    const uint32_t bcb = (uint32_t)((lane >> 3) & 1);    // B col chunk bit (0/1)

    // cp.async tile coordinates (+ swizzled chunk)
    const int lar = tid >> 2, lac = tid & 3;     // A: row (+64 for i=1), 16B chunk
    const int lbn = tid >> 2, lbc = tid & 3;     // B: n-row, 16B chunk
    const uint32_t aoffs = (uint32_t)(lar * 64 + ((lac ^ ((lar >> 1) & 3)) << 4));
    const uint32_t boffs = (uint32_t)(lbn * 64 + ((lbc ^ ((lbn >> 1) & 3)) << 4));

    const int nk = K / BK;

    auto issue_tile = [&](int kt, int s) {
        const int k0 = kt * BK;
        const uint32_t b0 = smb + (uint32_t)(s * BUF_B);
        const __nv_bfloat16* sAh = Ahi;
        const __nv_bfloat16* sAl = Alo;
        int ld = lda, kc = k0;
        if (CONCAT && k0 >= K1) { sAh = A2hi; sAl = A2lo; ld = lda2; kc = k0 - K1; }
        #pragma unroll
        for (int i = 0; i < 2; ++i) {
            int r = lar + i * 64;
            int ok = (m0 + r < M);
            int rr = ok ? (m0 + r) : 0;
            size_t off = (size_t)rr * ld + kc + 8 * lac;
            int sz = ok ? 16 : 0;
            uint32_t d = b0 + aoffs + (uint32_t)(i * 4096);   // i*64 rows * 64 B
            cp16(d,              &sAh[off], sz);
            cp16(d + A_SZ * 2,   &sAl[off], sz);
        }
        {
            size_t off = (size_t)(n0 + lbn) * ldb + k0 + 8 * lbc;
            uint32_t d = b0 + 2 * A_SZ * 2 + boffs;
            cp16(d,            &Wthi[off], 16);
            cp16(d + B_SZ * 2, &Wtlo[off], 16);
        }
    };

    // prologue: two tiles in flight
    issue_tile(0, 0); CP_COMMIT();
    if (nk > 1) { issue_tile(1, 1); CP_COMMIT(); }

    for (int kt = 0; kt < nk; ++kt) {
        const int s = kt % N_STAGE;
        if (kt < nk - 1) asm volatile("cp.async.wait_group 1;" ::: "memory");
        else             asm volatile("cp.async.wait_group 0;" ::: "memory");
        __syncthreads();
        // stage (kt+2)%3 == (kt-1)%3 was consumed in iter kt-1; all threads are
        // past that iteration's reads (they reached this barrier), so it's free.
        if (kt + 2 < nk) { issue_tile(kt + 2, (kt + 2) % N_STAGE); CP_COMMIT(); }

        const uint32_t bAhi = smb + (uint32_t)(s * BUF_B);
        const uint32_t bAlo = bAhi + A_SZ * 2;
        const uint32_t bBhi = bAlo + A_SZ * 2;
        const uint32_t bBlo = bBhi + B_SZ * 2;

        #pragma unroll
        for (int half = 0; half < 2; ++half) {
            uint32_t ah[2][4], al[2][4], bh[4][2], bl[4][2];
            const uint32_t ca = (uint32_t)(half * 2) + acb;   // A chunk index
            const uint32_t cb = (uint32_t)(half * 2) + bcb;   // B chunk index
            #pragma unroll
            for (int tm = 0; tm < 2; ++tm) {
                uint32_t off = arow[tm] + ((ca ^ akey[tm]) << 4);
                ldsm_x4(ah[tm][0], ah[tm][1], ah[tm][2], ah[tm][3], bAhi + off);
                ldsm_x4(al[tm][0], al[tm][1], al[tm][2], al[tm][3], bAlo + off);
            }
            #pragma unroll
            for (int pr = 0; pr < 2; ++pr) {
                uint32_t off = brow[pr] + ((cb ^ bkey[pr]) << 4);
                ldsm_x4(bh[2*pr][0], bh[2*pr][1], bh[2*pr+1][0], bh[2*pr+1][1],
                        bBhi + off);
                ldsm_x4(bl[2*pr][0], bl[2*pr][1], bl[2*pr+1][0], bl[2*pr+1][1],
                        bBlo + off);
            }
            #pragma unroll
            for (int tm = 0; tm < 2; ++tm)
                #pragma unroll
                for (int tn = 0; tn < 4; ++tn) {
                    mma_bf16(acc[tm][tn], ah[tm], bh[tn]);
                    mma_bf16(acc[tm][tn], ah[tm], bl[tn]);
                    mma_bf16(acc[tm][tn], al[tm], bh[tn]);
                }
        }
    }

    // --- epilogue: (c0,c1)/(c2,c3) are col pairs at rows r / r+8 ---
    #pragma unroll
    for (int tm = 0; tm < 2; ++tm) {
        #pragma unroll
        for (int half = 0; half < 2; ++half) {
            int row = m0 + wm + tm * 16 + g + half * 8;
            if (row >= M) continue;
            #pragma unroll
            for (int tn = 0; tn < 4; ++tn) {
                int col = n0 + wn + tn * 8 + 2 * tig;
                float v0 = acc[tm][tn][half * 2 + 0];
                float v1 = acc[tm][tn][half * 2 + 1];
                if (HAS_ADD) {
                    float2 a2 = *(const float2*)&addrow[(size_t)row * HID + col];
                    v0 += a2.x; v1 += a2.y;
                }
                if (HAS_BIAS) { v0 += __ldg(&bias[col]); v1 += __ldg(&bias[col + 1]); }
                if (RELU) { v0 = fmaxf(v0, 0.f); v1 = fmaxf(v1, 0.f); }
                *(float2*)&out[(size_t)row * HID + col] = make_float2(v0, v1);
            }
        }
    }
}

// ---------------------------------------------------------------------------
// gather-sum over 6 padded neighbors with ON-LOAD RELU, writes bf16 hi/lo
// planes. Sources hold PRE-relu messages; relu is applied here.
// block (112, 4); per-row indices deduped via smem.
// ---------------------------------------------------------------------------
__global__ void gather6_split(const float4* __restrict__ src,
                              const int* __restrict__ idx,
                              __nv_bfloat16* __restrict__ hi,
                              __nv_bfloat16* __restrict__ lo, int n)
{
    __shared__ int sIdx[24];
    int flat = threadIdx.y * 112 + threadIdx.x;
    if (flat < 24) {
        int r = flat / 6, j = flat % 6;
        int row = blockIdx.x * 4 + r;
        sIdx[flat] = (row < n) ? __ldg(&idx[(size_t)row * 6 + j]) : 0;
    }
    __syncthreads();

    int row = blockIdx.x * 4 + threadIdx.y;
    if (row >= n) return;
    int c = threadIdx.x;  // 0..111
    float4 acc = make_float4(0.f, 0.f, 0.f, 0.f);
    #pragma unroll
    for (int j = 0; j < 6; ++j) {
        int b = sIdx[threadIdx.y * 6 + j];
        float4 v = __ldg(&src[(size_t)b * HID4 + c]);
        acc.x += fmaxf(v.x, 0.f); acc.y += fmaxf(v.y, 0.f);
        acc.z += fmaxf(v.z, 0.f); acc.w += fmaxf(v.w, 0.f);
    }
    __nv_bfloat16 h0, l0, h1, l1, h2, l2, h3, l3;
    split_bf16(acc.x, h0, l0); split_bf16(acc.y, h1, l1);
    split_bf16(acc.z, h2, l2); split_bf16(acc.w, h3, l3);
    __nv_bfloat162 ph01 = __halves2bfloat162(h0, h1);
    __nv_bfloat162 ph23 = __halves2bfloat162(h2, h3);
    __nv_bfloat162 pl01 = __halves2bfloat162(l0, l1);
    __nv_bfloat162 pl23 = __halves2bfloat162(l2, l3);
    uint2 uh = make_uint2(*(uint32_t*)&ph01, *(uint32_t*)&ph23);
    uint2 ul = make_uint2(*(uint32_t*)&pl01, *(uint32_t*)&pl23);
    *(uint2*)&hi[(size_t)row * HID + 4 * c] = uh;
    *(uint2*)&lo[(size_t)row * HID + 4 * c] = ul;
}

// ---------------------------------------------------------------------------
// segment mean over sorted mol_idx
// ---------------------------------------------------------------------------
__global__ void segment_mean(const float4* __restrict__ atomh,
                             const int* __restrict__ mol,
                             float4* __restrict__ out, int n_atoms)
{
    int m = blockIdx.x;
    int c = threadIdx.x;  // 0..111
    int lo = 0, hi = n_atoms;
    while (lo < hi) { int mid = (lo + hi) >> 1; if (__ldg(&mol[mid]) < m) lo = mid + 1; else hi = mid; }
    int lo2 = lo, hi2 = n_atoms;
    while (lo2 < hi2) { int mid = (lo2 + hi2) >> 1; if (__ldg(&mol[mid]) < m + 1) lo2 = mid + 1; else hi2 = mid; }
    float4 acc = make_float4(0.f, 0.f, 0.f, 0.f);
    for (int a = lo; a < lo2; ++a) {
        float4 v = __ldg(&atomh[(size_t)a * HID4 + c]);
        acc.x += v.x; acc.y += v.y; acc.z += v.z; acc.w += v.w;
    }
    float inv = 1.f / fmaxf((float)(lo2 - lo), 1.f);
    out[(size_t)m * HID4 + c] = make_float4(acc.x * inv, acc.y * inv, acc.z * inv, acc.w * inv);
}

// ---------------------------------------------------------------------------
// host launcher
// ---------------------------------------------------------------------------
static void set_smem(const void* f, int bytes) {
    cudaFuncSetAttribute(f, cudaFuncAttributeMaxDynamicSharedMemorySize, bytes);
}
#define SYMADDR(p, s) cudaGetSymbolAddress((void**)&(p), s)

extern "C" void kernel_launch(void* const* d_in, const int* in_sizes, int n_in,
                              void* d_out, int out_size)
{
    const float* fatoms  = (const float*)d_in[0];
    const float* fbonds  = (const float*)d_in[1];
    const float* W_i     = (const float*)d_in[2];
    const float* W_h     = (const float*)d_in[3];
    const float* W_o     = (const float*)d_in[4];
    const float* b_o     = (const float*)d_in[5];
    const void*  agraph  = d_in[6];
    const void*  bgraph  = d_in[7];
    const void*  mol_idx = d_in[8];

    const int n_atoms = in_sizes[8];            // 80000
    const int n_bonds = in_sizes[7] / 6;        // 160001
    const int n_mols  = out_size / HID;         // 4000
    const int K_in    = in_sizes[2] / HID;      // 49
    const int K_atom  = in_sizes[0] / n_atoms;  // 38

    float *binput, *msgA, *msgB, *atomh;
    __nv_bfloat16 *neih, *neil, *fbh, *fbl, *fah, *fal;
    __nv_bfloat16 *Wih, *Wil, *Whh, *Whl, *Woch, *Wocl;
    int *bgr, *agr, *mol;
    SYMADDR(binput, g_binput); SYMADDR(msgA, g_msgA); SYMADDR(msgB, g_msgB);
    SYMADDR(atomh, g_atomh);
    SYMADDR(neih, g_neih); SYMADDR(neil, g_neil);
    SYMADDR(fbh, g_fbh);   SYMADDR(fbl, g_fbl);
    SYMADDR(fah, g_fah);   SYMADDR(fal, g_fal);
    SYMADDR(Wih, g_Wih);   SYMADDR(Wil, g_Wil);
    SYMADDR(Whh, g_Whh);   SYMADDR(Whl, g_Whl);
    SYMADDR(Woch, g_Woch); SYMADDR(Wocl, g_Wocl);
    SYMADDR(bgr, g_bgraph); SYMADDR(agr, g_agraph); SYMADDR(mol, g_mol);

    set_smem((const void*)gemm_pre<false, false, false, false>, GEMM_SMEM);
    set_smem((const void*)gemm_pre<false, false, true,  false>, GEMM_SMEM);
    set_smem((const void*)gemm_pre<true,  true,  false, true >, GEMM_SMEM);

    // 0) index normalization + one-shot operand prep
    detect_idx64<<<1, 32>>>((const unsigned int*)bgraph, 512);
    {
        int total = n_bonds * 6 + n_atoms * 6 + n_atoms;
        norm_all<<<(total + 255) / 256, 256>>>(bgraph, agraph, mol_idx,
                                               bgr, agr, mol,
                                               n_bonds * 6, n_atoms * 6, n_atoms);
    }
    {
        size_t total = (size_t)n_bonds * KPAD_S + (size_t)n_atoms * KPAD_S
                     + (size_t)HID * KPAD_S + (size_t)HID * HID + (size_t)HID * KCAT;
        prep_all<<<(unsigned)((total + 255) / 256), 256>>>(
            fbonds, fatoms, W_i, W_h, W_o,
            fbh, fbl, fah, fal, Wih, Wil, Whh, Whl, Woch, Wocl,
            n_bonds, n_atoms, K_in, K_atom);
    }

    dim3 blk(256);
    dim3 grdB(HID / BN, (n_bonds + BM - 1) / BM);   // (7, 1251)
    dim3 grdA(HID / BN, (n_atoms + BM - 1) / BM);   // (7, 625)
    dim3 gblk(HID4, 4);

    // 1) binput = fbonds @ W_i  (raw only; relu applied by consumers)
    gemm_pre<false, false, false, false><<<grdB, blk, GEMM_SMEM>>>(
        fbh, fbl, KPAD_S, nullptr, nullptr, 0, 1 << 30,
        Wih, Wil, KPAD_S, nullptr, nullptr,
        binput, n_bonds, KPAD_S);

    // 2) message-passing iterations (DEPTH-1 = 4); messages stored PRE-relu,
    //    gather applies relu on load.
    float* cur = binput;      // message_0 = relu(binput) — relu in gather
    float* nxt = msgA;
    float* spare = msgB;
    for (int it = 0; it < 4; ++it) {
        gather6_split<<<(n_bonds + 3) / 4, gblk>>>((const float4*)cur, bgr,
                                                   neih, neil, n_bonds);
        gemm_pre<false, false, true, false><<<grdB, blk, GEMM_SMEM>>>(
            neih, neil, HID, nullptr, nullptr, 0, 1 << 30,
            Whh, Whl, HID, binput, nullptr,
            nxt, n_bonds, HID);
        float* old = cur;
        cur = nxt;
        nxt = (it == 0) ? spare : old;    // never overwrite binput
    }

    // 3) atom readout: gather (relu on load), then fused
    //    atomh = relu([nei | fatoms] @ Woc + b_o)
    gather6_split<<<(n_atoms + 3) / 4, gblk>>>((const float4*)cur, agr,
                                               neih, neil, n_atoms);
    gemm_pre<true, true, false, true><<<grdA, blk, GEMM_SMEM>>>(
        neih, neil, HID, fah, fal, KPAD_S, HID,
        Woch, Wocl, KCAT, nullptr, b_o,
        atomh, n_atoms, KCAT);

    // 4) per-molecule mean (sorted mol_idx, no atomics)
    segment_mean<<<n_mols, HID4>>>((const float4*)atomh, mol,
                                   (float4*)d_out, n_atoms);
}